// round 5
// baseline (speedup 1.0000x reference)
#include <cuda_runtime.h>
#include <math.h>

// Problem constants
#define BATCH 16
#define LROWS 192   // 6*L rows of raw
#define AC    2046  // attributor columns
#define MC    2048  // M = A + 2
#define LD    32    // L (W_2 output dim)
#define TM    128   // columns of m per block in main kernel
#define MB    (MC / TM)   // 16 m-blocks

// Scratch (device globals; no allocation allowed)
// Partial S: g_pS[b][mb][n][j] — plain stores, reduced in final kernel.
__device__ float g_pS[BATCH][MB][2][64];

// ---------------------------------------------------------------------------
// Main kernel: fully self-contained. grid (mb=16, b=16), 384 threads.
// Per-block prologue recomputes the special-column wq/wk folds (batch-local,
// W2 is L2-resident) and gathers adj/iw for its 128 m's. Then the streaming
// pass with register-batched loads, sigmoid-causal, and partial-S stores.
// ---------------------------------------------------------------------------
__global__ __launch_bounds__(384) void main_kernel(
    const float* __restrict__ user, const float* __restrict__ item,
    const float* __restrict__ attributor, const float* __restrict__ W1,
    const float* __restrict__ W2,
    const float* __restrict__ adj, const float* __restrict__ iw) {

    __shared__ float Vsh[64][TM + 1];
    __shared__ float hq_sh[2][TM];
    __shared__ float hk_sh[2][TM];
    __shared__ float c_sh[2][TM];
    __shared__ float wq_sh[2][64];
    __shared__ float wk_sh[2][64];
    __shared__ float xr[2][128];      // relu of rows 0..127 of user(0)/item(1)
    __shared__ float qs[2][32];
    __shared__ float ks[2][32];
    __shared__ float aA[2][TM];       // adj[m][col_n]
    __shared__ float aP[2][TM];       // adj*iw [m][col_n]
    __shared__ float aR[2][TM];       // adj*iw [col_n][m]

    int b  = blockIdx.y;
    int mb = blockIdx.x;
    int t  = threadIdx.x;
    int group = t >> 7;          // 0,1,2
    int ml = t & (TM - 1);
    int m  = mb * TM + ml;

    // ---- prologue phase 1: raw loads (disjoint thread groups, all parallel)
    if (t < 256) {
        int n = t >> 7, r = t & 127;
        const float* src = (n ? item : user) + b * LROWS + r;
        xr[n][r] = fmaxf(*src, 0.0f);
    } else {
        int mm = t - 256;               // 0..127
        int mg = mb * TM + mm;
        size_t row = (size_t)mg * MC;
        float a0 = adj[row];
        float a1 = adj[row + (MC - 1)];
        aA[0][mm] = a0;
        aA[1][mm] = a1;
        aP[0][mm] = a0 * iw[row];
        aP[1][mm] = a1 * iw[row + (MC - 1)];
        aR[0][mm] = adj[mg] * iw[mg];
        size_t lastrow = (size_t)(MC - 1) * MC + mg;
        aR[1][mm] = adj[lastrow] * iw[lastrow];
    }
    __syncthreads();

    // ---- prologue phase 2: qs/ks (128 outputs: n x {q,k} x l)
    if (t < 128) {
        int n  = t >> 6;
        int qk = (t >> 5) & 1;
        int l  = t & 31;
        float s = 0.0f;
        if (qk == 0) {
            #pragma unroll
            for (int j = 0; j < 64; j++) s = fmaf(xr[n][j], W2[j * LD + l], s);
            qs[n][l] = s;
        } else {
            #pragma unroll
            for (int j = 0; j < 64; j++) s = fmaf(xr[n][64 + j], W2[(64 + j) * LD + l], s);
            ks[n][l] = s;
        }
    }
    __syncthreads();

    // ---- prologue phase 3: wq/wk (256 outputs: n x {wq,wk} x j)
    if (t < 256) {
        int n   = t >> 7;
        int sel = (t >> 6) & 1;
        int j   = t & 63;
        float s = 0.0f;
        if (sel == 0) {
            #pragma unroll
            for (int l = 0; l < 32; l++) s = fmaf(W2[j * LD + l], ks[n][l], s);
            wq_sh[n][j] = s;
        } else {
            #pragma unroll
            for (int l = 0; l < 32; l++) s = fmaf(W2[(64 + j) * LD + l], qs[n][l], s);
            wk_sh[n][j] = s;
        }
    }
    __syncthreads();

    // ---- streaming pass ----
    bool isU = (m == 0), isI = (m == MC - 1);
    bool special = isU || isI;

    if (group < 2) {
        const float (*wsel)[64] = (group == 0) ? wq_sh : wk_sh;
        float h0 = 0.0f, h1 = 0.0f;
        if (special) {
            const float* up = (isU ? user : item) + b * LROWS + group * 64;
            #pragma unroll
            for (int j = 0; j < 64; j++) {
                float x = fmaxf(up[j], 0.0f);
                h0 = fmaf(x, wsel[0][j], h0);
                h1 = fmaf(x, wsel[1][j], h1);
            }
        } else {
            const float* ap = attributor + ((size_t)b * LROWS + group * 64) * AC + (m - 1);
            const float* wp = W1 + (size_t)(group * 64) * AC + (m - 1);
            #pragma unroll 2
            for (int jb = 0; jb < 64; jb += 8) {
                float av[8], wv[8];
                #pragma unroll
                for (int u = 0; u < 8; u++) av[u] = ap[(size_t)(jb + u) * AC];
                #pragma unroll
                for (int u = 0; u < 8; u++) wv[u] = wp[(size_t)(jb + u) * AC];
                #pragma unroll
                for (int u = 0; u < 8; u++) {
                    float x = fmaxf(av[u] * wv[u], 0.0f);
                    h0 = fmaf(x, wsel[0][jb + u], h0);
                    h1 = fmaf(x, wsel[1][jb + u], h1);
                }
            }
        }
        if (group == 0) { hq_sh[0][ml] = h0; hq_sh[1][ml] = h1; }
        else            { hk_sh[0][ml] = h0; hk_sh[1][ml] = h1; }
    } else {
        if (special) {
            const float* up = (isU ? user : item) + b * LROWS + 128;
            #pragma unroll
            for (int j = 0; j < 64; j++) Vsh[j][ml] = fmaxf(up[j], 0.0f);
        } else {
            const float* ap = attributor + ((size_t)b * LROWS + 128) * AC + (m - 1);
            const float* wp = W1 + (size_t)128 * AC + (m - 1);
            #pragma unroll 2
            for (int jb = 0; jb < 64; jb += 8) {
                float av[8], wv[8];
                #pragma unroll
                for (int u = 0; u < 8; u++) av[u] = ap[(size_t)(jb + u) * AC];
                #pragma unroll
                for (int u = 0; u < 8; u++) wv[u] = wp[(size_t)(jb + u) * AC];
                #pragma unroll
                for (int u = 0; u < 8; u++)
                    Vsh[jb + u][ml] = fmaxf(av[u] * wv[u], 0.0f);
            }
        }
    }
    __syncthreads();

    // causal[b, m, col_n] = sigmoid(h[m,n] - h[n,m]) * adj[m, col_n]
    if (t < 256) {
        int n  = t >> 7;
        int mm = t & (TM - 1);
        float d = hq_sh[n][mm] * aP[n][mm] - hk_sh[n][mm] * aR[n][mm];
        c_sh[n][mm] = aA[n][mm] / (1.0f + expf(-d));
    }
    __syncthreads();

    // partial S[b][mb][n][j] = sum_mm Vsh[j][mm] * c_sh[n][mm]  (plain store)
    if (t < 128) {
        int n = t >> 6;
        int j = t & 63;
        float s = 0.0f;
        #pragma unroll 8
        for (int mm = 0; mm < TM; mm++)
            s = fmaf(Vsh[j][mm], c_sh[n][mm], s);
        g_pS[b][mb][n][j] = s;
    }
}

// ---------------------------------------------------------------------------
// Final kernel: reduce 16 partials, then out[b,l,n] = sum_j W2[128+j,l]*S[b][n][j]
// 1 block x 1024 threads; all staging in shared, coalesced.
// ---------------------------------------------------------------------------
__global__ __launch_bounds__(1024) void final_kernel(
    const float* __restrict__ W2, float* __restrict__ out) {
    __shared__ float Ssh[BATCH * 2 * 64];   // 2048 reduced S values
    __shared__ float Wsh[64][LD];           // 2048
    int t = threadIdx.x;
    const float* pS = (const float*)g_pS;

    // reduce partials: idx = (b*2+n)*64+j  over mb (stride 128 within a batch)
    #pragma unroll
    for (int k = 0; k < 2; k++) {
        int idx = t + k * 1024;             // 0..2047
        int bb  = idx >> 7;                 // batch
        int nj  = idx & 127;                // (n*64+j)
        const float* p = pS + (size_t)bb * (MB * 128) + nj;
        float s = 0.0f;
        #pragma unroll
        for (int mbi = 0; mbi < MB; mbi++) s += p[mbi * 128];
        Ssh[idx] = s;
    }
    {
        int j = t >> 5, l = t & 31;
        Wsh[j][l]      = W2[(128 + j) * LD + l];
        Wsh[j + 32][l] = W2[(160 + j) * LD + l];
    }
    __syncthreads();

    int b = t >> 6;
    int l = (t >> 1) & 31;
    int n = t & 1;
    const float* Sv = &Ssh[(b * 2 + n) * 64];
    float s = 0.0f;
    #pragma unroll
    for (int j = 0; j < 64; j++)
        s = fmaf(Wsh[j][l], Sv[j], s);
    out[t] = s;
}

extern "C" void kernel_launch(void* const* d_in, const int* in_sizes, int n_in,
                              void* d_out, int out_size) {
    const float* user       = (const float*)d_in[0];
    const float* item       = (const float*)d_in[1];
    const float* attributor = (const float*)d_in[2];
    const float* adj        = (const float*)d_in[3];
    const float* iw         = (const float*)d_in[4];
    const float* W1         = (const float*)d_in[5];
    const float* W2         = (const float*)d_in[6];
    float* out = (float*)d_out;

    main_kernel<<<dim3(MB, BATCH), 384>>>(user, item, attributor, W1, W2, adj, iw);
    final_kernel<<<1, 1024>>>(W2, out);
}

// round 6
// speedup vs baseline: 2.2800x; 2.2800x over previous
#include <cuda_runtime.h>
#include <math.h>

// Problem constants
#define BATCH 16
#define LROWS 192   // 6*L rows of raw
#define AC    2046  // attributor columns
#define MC    2048  // M = A + 2
#define LD    32    // L (W_2 output dim)
#define TM    128   // columns of m per block in main kernel
#define MB    (MC / TM)   // 16 m-blocks

// Scratch (device globals; no allocation allowed)
__device__ float g_wq[BATCH][2][64];   // wq[b][n][j] = sum_l W2[j,l] * Key[b,l,col_n]
__device__ float g_wk[BATCH][2][64];   // wk[b][n][j] = sum_l W2[64+j,l] * Query[b,l,col_n]
__device__ float g_A[2][MC];           // adj[m][col_n]
__device__ float g_P[2][MC];           // adj[m][col_n] * iw[m][col_n]
__device__ float g_R[2][MC];           // adj[col_n][m] * iw[col_n][m]

// ---------------------------------------------------------------------------
// Kernel 1 (prep): wq/wk folds + adj/iw packing + d_out zeroing.
// grid 48 x 128. W2[0:128] prefetched to smem in parallel with user/item
// loads so the fold phases are LDS-latency, not DRAM-latency.
// ---------------------------------------------------------------------------
__global__ __launch_bounds__(128) void prep_kernel(
    const float* __restrict__ user, const float* __restrict__ item,
    const float* __restrict__ W2,
    const float* __restrict__ adj, const float* __restrict__ iw,
    float* __restrict__ out) {

    int blk = blockIdx.x;
    int t = threadIdx.x;

    if (blk < 32) {
        int b = blk >> 1;
        int n = blk & 1;
        const float* src = (n ? item : user) + b * LROWS;
        __shared__ float W2s[128 * 33];   // padded rows: conflict-free both ways
        __shared__ float xr[128];
        __shared__ float qs[32];
        __shared__ float ks[32];

        // issue ALL gmem loads up front (parallel DRAM latency)
        xr[t] = fmaxf(src[t], 0.0f);
        #pragma unroll
        for (int i = 0; i < 32; i++) {
            int idx = t + i * 128;            // 0..4095
            W2s[(idx >> 5) * 33 + (idx & 31)] = W2[idx];
        }
        __syncthreads();

        if (t < 32) {
            float s = 0.0f;
            #pragma unroll
            for (int j = 0; j < 64; j++) s = fmaf(xr[j], W2s[j * 33 + t], s);
            qs[t] = s;
        } else if (t < 64) {
            int l = t - 32;
            float s = 0.0f;
            #pragma unroll
            for (int j = 0; j < 64; j++) s = fmaf(xr[64 + j], W2s[(64 + j) * 33 + l], s);
            ks[l] = s;
        }
        __syncthreads();
        if (t < 64) {
            float swq = 0.0f, swk = 0.0f;
            #pragma unroll
            for (int l = 0; l < 32; l++) {
                swq = fmaf(W2s[t * 33 + l],        ks[l], swq);
                swk = fmaf(W2s[(64 + t) * 33 + l], qs[l], swk);
            }
            g_wq[b][n][t] = swq;
            g_wk[b][n][t] = swk;
        }
    } else {
        if (blk == 32) {          // zero d_out (1024 floats) for the atomics
            float4 z = make_float4(0.f, 0.f, 0.f, 0.f);
            ((float4*)out)[t]       = z;
            ((float4*)out)[t + 128] = z;
        }
        int m = (blk - 32) * 128 + t;
        size_t row = (size_t)m * MC;
        float a0 = adj[row];
        float a1 = adj[row + (MC - 1)];
        g_A[0][m] = a0;
        g_A[1][m] = a1;
        g_P[0][m] = a0 * iw[row];
        g_P[1][m] = a1 * iw[row + (MC - 1)];
        g_R[0][m] = adj[m] * iw[m];
        size_t lastrow = (size_t)(MC - 1) * MC + m;
        g_R[1][m] = adj[lastrow] * iw[lastrow];
    }
}

// ---------------------------------------------------------------------------
// Kernel 2 (main): streaming pass + fused projection epilogue.
// grid (mb=16, b=16), 384 threads.
//   t<128 load wq/wk; t in [128,256) preload W2[128:192] slice to smem
//   (both overlap the streaming-phase DRAM traffic).
// ---------------------------------------------------------------------------
__global__ __launch_bounds__(384) void main_kernel(
    const float* __restrict__ user, const float* __restrict__ item,
    const float* __restrict__ attributor, const float* __restrict__ W1,
    const float* __restrict__ W2, float* __restrict__ out) {

    __shared__ float Vsh[64][TM + 1];
    __shared__ float hq_sh[2][TM];
    __shared__ float hk_sh[2][TM];
    __shared__ float c_sh[2][TM];
    __shared__ float wq_sh[2][64];
    __shared__ float wk_sh[2][64];
    __shared__ float W2e[64][LD];    // W2 rows 128..191 (value projection)
    __shared__ float Ssh[2 * 64];    // partial S for this block

    int b  = blockIdx.y;
    int mb = blockIdx.x;
    int t  = threadIdx.x;
    int group = t >> 7;          // 0,1,2
    int ml = t & (TM - 1);
    int m  = mb * TM + ml;

    if (t < 128) {
        ((float*)wq_sh)[t] = ((const float*)g_wq[b])[t];
        ((float*)wk_sh)[t] = ((const float*)g_wk[b])[t];
    } else if (t < 256) {
        int r = t - 128;                       // 0..127, 16 floats each
        #pragma unroll
        for (int i = 0; i < 4; i++)
            ((float4*)W2e)[r + i * 128] = ((const float4*)(W2 + 128 * LD))[r + i * 128];
    }
    __syncthreads();

    bool isU = (m == 0), isI = (m == MC - 1);
    bool special = isU || isI;

    if (group < 2) {
        const float (*wsel)[64] = (group == 0) ? wq_sh : wk_sh;
        float h0 = 0.0f, h1 = 0.0f;
        if (special) {
            const float* up = (isU ? user : item) + b * LROWS + group * 64;
            #pragma unroll
            for (int j = 0; j < 64; j++) {
                float x = fmaxf(up[j], 0.0f);
                h0 = fmaf(x, wsel[0][j], h0);
                h1 = fmaf(x, wsel[1][j], h1);
            }
        } else {
            const float* ap = attributor + ((size_t)b * LROWS + group * 64) * AC + (m - 1);
            const float* wp = W1 + (size_t)(group * 64) * AC + (m - 1);
            #pragma unroll 2
            for (int jb = 0; jb < 64; jb += 8) {
                float av[8], wv[8];
                #pragma unroll
                for (int u = 0; u < 8; u++) av[u] = ap[(size_t)(jb + u) * AC];
                #pragma unroll
                for (int u = 0; u < 8; u++) wv[u] = wp[(size_t)(jb + u) * AC];
                #pragma unroll
                for (int u = 0; u < 8; u++) {
                    float x = fmaxf(av[u] * wv[u], 0.0f);
                    h0 = fmaf(x, wsel[0][jb + u], h0);
                    h1 = fmaf(x, wsel[1][jb + u], h1);
                }
            }
        }
        if (group == 0) { hq_sh[0][ml] = h0; hq_sh[1][ml] = h1; }
        else            { hk_sh[0][ml] = h0; hk_sh[1][ml] = h1; }
    } else {
        if (special) {
            const float* up = (isU ? user : item) + b * LROWS + 128;
            #pragma unroll
            for (int j = 0; j < 64; j++) Vsh[j][ml] = fmaxf(up[j], 0.0f);
        } else {
            const float* ap = attributor + ((size_t)b * LROWS + 128) * AC + (m - 1);
            const float* wp = W1 + (size_t)128 * AC + (m - 1);
            #pragma unroll 2
            for (int jb = 0; jb < 64; jb += 8) {
                float av[8], wv[8];
                #pragma unroll
                for (int u = 0; u < 8; u++) av[u] = ap[(size_t)(jb + u) * AC];
                #pragma unroll
                for (int u = 0; u < 8; u++) wv[u] = wp[(size_t)(jb + u) * AC];
                #pragma unroll
                for (int u = 0; u < 8; u++)
                    Vsh[jb + u][ml] = fmaxf(av[u] * wv[u], 0.0f);
            }
        }
    }
    __syncthreads();

    // causal[b, m, col_n] = sigmoid(h[m,n] - h[n,m]) * adj[m, col_n]
    if (t < 256) {
        int n  = t >> 7;
        int mm = t & (TM - 1);
        int mg = mb * TM + mm;
        float d = hq_sh[n][mm] * g_P[n][mg] - hk_sh[n][mm] * g_R[n][mg];
        c_sh[n][mm] = g_A[n][mg] / (1.0f + expf(-d));
    }
    __syncthreads();

    // partial S[n][j] = sum_mm Vsh[j][mm] * c_sh[n][mm]
    if (t < 128) {
        int n = t >> 6;
        int j = t & 63;
        float s = 0.0f;
        #pragma unroll 8
        for (int mm = 0; mm < TM; mm++)
            s = fmaf(Vsh[j][mm], c_sh[n][mm], s);
        Ssh[t] = s;
    }
    __syncthreads();

    // fused projection: out[b,l,n] += sum_j W2e[j][l] * S[n][j]
    if (t < 64) {
        int l = t >> 1;
        int n = t & 1;
        float s = 0.0f;
        #pragma unroll
        for (int j = 0; j < 64; j++)
            s = fmaf(W2e[j][l], Ssh[n * 64 + j], s);
        atomicAdd(&out[b * 64 + l * 2 + n], s);
    }
}

extern "C" void kernel_launch(void* const* d_in, const int* in_sizes, int n_in,
                              void* d_out, int out_size) {
    const float* user       = (const float*)d_in[0];
    const float* item       = (const float*)d_in[1];
    const float* attributor = (const float*)d_in[2];
    const float* adj        = (const float*)d_in[3];
    const float* iw         = (const float*)d_in[4];
    const float* W1         = (const float*)d_in[5];
    const float* W2         = (const float*)d_in[6];
    float* out = (float*)d_out;

    prep_kernel<<<48, 128>>>(user, item, W2, adj, iw, out);
    main_kernel<<<dim3(MB, BATCH), 384>>>(user, item, attributor, W1, W2, out);
}